// round 1
// baseline (speedup 1.0000x reference)
#include <cuda_runtime.h>
#include <math.h>

// Problem constants
#define T_STEPS 1000
#define BATCH   128
#define N_IN    3
#define N_H     256
#define N_PC    256
#define N_HD    12
#define N_IC    268
#define M_ROWS  (T_STEPS * BATCH)   // 128000

// Output layout (float32, concatenated in reference tuple order)
#define OFF_HD   0L
#define OFF_PC   (OFF_HD  + (long)T_STEPS * BATCH * N_HD)   //   1,536,000
#define OFF_BOT  (OFF_PC  + (long)T_STEPS * BATCH * N_PC)   //  34,304,000
#define OFF_RNN  (OFF_BOT + (long)T_STEPS * BATCH * N_H)    //  67,072,000
#define OFF_CELL (OFF_RNN + (long)T_STEPS * BATCH * N_H)    //  99,840,000

// Scratch for initial carry (allocation-free: device globals)
__device__ float g_h0[BATCH * N_H];
__device__ float g_c0[BATCH * N_H];

// ---------------------------------------------------------------------------
// Kernel 1: initial conditions  h0 = sigmoid(ic@sew + seb), c0 = sigmoid(ic@cew + ceb)
// grid = BATCH blocks, 256 threads (one per h)
// ---------------------------------------------------------------------------
__global__ void init_kernel(const float* __restrict__ ic,
                            const float* __restrict__ sew, const float* __restrict__ seb,
                            const float* __restrict__ cew, const float* __restrict__ ceb) {
    __shared__ float icr[N_IC];
    int b = blockIdx.x;
    int h = threadIdx.x;
    for (int i = h; i < N_IC; i += N_H) icr[i] = ic[b * N_IC + i];
    __syncthreads();

    float accS = seb[h];
    float accC = ceb[h];
    #pragma unroll 4
    for (int k = 0; k < N_IC; k++) {
        float v = icr[k];
        accS = fmaf(v, sew[k * N_H + h], accS);
        accC = fmaf(v, cew[k * N_H + h], accC);
    }
    g_h0[b * N_H + h] = 1.0f / (1.0f + expf(-accS));
    g_c0[b * N_H + h] = 1.0f / (1.0f + expf(-accC));
}

// ---------------------------------------------------------------------------
// Kernel 2: the recurrence. Elementwise in (b,h) -> fully independent chains.
// grid = BATCH blocks, 64 threads; each thread owns 4 consecutive h (float4 IO).
// x[:, b, :] (12 KB) staged in shared memory up front.
// Writes y -> BOT and RNN regions, s -> CELL region.
// ---------------------------------------------------------------------------
__global__ void __launch_bounds__(64, 8) rec_kernel(const float* __restrict__ x,
                                                    const float* __restrict__ iw,
                                                    const float* __restrict__ lvec,
                                                    const float* __restrict__ bvec,
                                                    float* __restrict__ out) {
    __shared__ float xs[T_STEPS * N_IN];  // 12 KB
    const int b   = blockIdx.x;
    const int tid = threadIdx.x;
    const int hbase = tid * 4;

    // Stage x[:, b, :] into shared
    for (int i = tid; i < T_STEPS * N_IN; i += 64) {
        int t = i / N_IN, c = i - t * N_IN;
        xs[i] = x[((long)t * BATCH + b) * N_IN + c];
    }

    float w0[4], w1[4], w2[4], lv[4], bv[4], y[4], s[4];
    #pragma unroll
    for (int i = 0; i < 4; i++) {
        int h = hbase + i;
        w0[i] = iw[0 * N_H + h];
        w1[i] = iw[1 * N_H + h];
        w2[i] = iw[2 * N_H + h];
        lv[i] = lvec[h];
        bv[i] = bvec[h];
        y[i]  = g_h0[b * N_H + h];
        s[i]  = g_c0[b * N_H + h];
    }
    __syncthreads();

    float4* yout1 = (float4*)(out + OFF_BOT);
    float4* yout2 = (float4*)(out + OFF_RNN);
    float4* sout  = (float4*)(out + OFF_CELL);

    for (int t = 0; t < T_STEPS; t++) {
        const float x0 = xs[t * 3 + 0];
        const float x1 = xs[t * 3 + 1];
        const float x2 = xs[t * 3 + 2];
        #pragma unroll
        for (int i = 0; i < 4; i++) {
            float xw  = fmaf(x2, w2[i], fmaf(x1, w1[i], x0 * w0[i]));
            float pre = xw + y[i] + lv[i] * s[i] * (1.0f - y[i]);
            s[i] = fmaxf(pre, 0.0f);
            y[i] = (s[i] + bv[i] > 0.0f) ? 1.0f : 0.0f;
        }
        long idx4 = (((long)t * BATCH + b) * N_H + hbase) >> 2;
        float4 yv = make_float4(y[0], y[1], y[2], y[3]);
        float4 sv = make_float4(s[0], s[1], s[2], s[3]);
        yout1[idx4] = yv;
        yout2[idx4] = yv;
        sout[idx4]  = sv;
    }
}

// ---------------------------------------------------------------------------
// Kernel 3: pc GEMM.  out[M=128000, N=256] = Y[M,256] @ W[256,256] + bias
// Classic 128x128 tile, BK=16, 256 threads, 8x8 per-thread register blocking.
// ---------------------------------------------------------------------------
#define BM 128
#define BN 128
#define BK 16
#define PAD 132  // padded SMEM row (in floats), keeps float4 alignment, breaks store conflicts

__global__ void __launch_bounds__(256, 2) pc_gemm(const float* __restrict__ Y,
                                                  const float* __restrict__ W,
                                                  const float* __restrict__ bias,
                                                  float* __restrict__ out) {
    __shared__ float As[BK * PAD];  // As[k][m]
    __shared__ float Bs[BK * PAD];  // Bs[k][n]

    const int tid = threadIdx.x;
    const int bm  = blockIdx.x;           // 0..999
    const int bn  = blockIdx.y;           // 0..1
    const int tx  = tid & 15;             // 0..15 -> n
    const int ty  = tid >> 4;             // 0..15 -> m

    float acc[8][8];
    #pragma unroll
    for (int i = 0; i < 8; i++)
        #pragma unroll
        for (int j = 0; j < 8; j++) acc[i][j] = 0.0f;

    const long rowBase = (long)bm * BM;
    const int  colBase = bn * BN;

    for (int kt = 0; kt < N_PC / BK; kt++) {
        // Load A tile (128 rows x 16 k) = 512 float4, 2 per thread, transpose into As[k][m]
        #pragma unroll
        for (int li = 0; li < 2; li++) {
            int idx4 = tid + 256 * li;         // 0..511
            int row  = idx4 >> 2;              // 0..127
            int kq   = idx4 & 3;               // float4 index along k
            float4 v = *(const float4*)(Y + (rowBase + row) * N_H + kt * BK + kq * 4);
            As[(kq * 4 + 0) * PAD + row] = v.x;
            As[(kq * 4 + 1) * PAD + row] = v.y;
            As[(kq * 4 + 2) * PAD + row] = v.z;
            As[(kq * 4 + 3) * PAD + row] = v.w;
        }
        // Load B tile (16 k x 128 n) = 512 float4, contiguous in n
        #pragma unroll
        for (int li = 0; li < 2; li++) {
            int idx4 = tid + 256 * li;         // 0..511
            int kr   = idx4 >> 5;              // 0..15
            int nq   = idx4 & 31;              // float4 index along n
            float4 v = *(const float4*)(W + (long)(kt * BK + kr) * N_PC + colBase + nq * 4);
            *(float4*)(Bs + kr * PAD + nq * 4) = v;
        }
        __syncthreads();

        #pragma unroll
        for (int k = 0; k < BK; k++) {
            float a[8], bfr[8];
            *(float4*)(a)       = *(const float4*)(As + k * PAD + ty * 8);
            *(float4*)(a + 4)   = *(const float4*)(As + k * PAD + ty * 8 + 4);
            *(float4*)(bfr)     = *(const float4*)(Bs + k * PAD + tx * 8);
            *(float4*)(bfr + 4) = *(const float4*)(Bs + k * PAD + tx * 8 + 4);
            #pragma unroll
            for (int i = 0; i < 8; i++)
                #pragma unroll
                for (int j = 0; j < 8; j++)
                    acc[i][j] = fmaf(a[i], bfr[j], acc[i][j]);
        }
        __syncthreads();
    }

    // Epilogue: add bias, write float4
    #pragma unroll
    for (int i = 0; i < 8; i++) {
        long gr = rowBase + ty * 8 + i;
        float* orow = out + gr * N_PC + colBase + tx * 8;
        float4 b0, b1;
        b0.x = acc[i][0] + bias[colBase + tx * 8 + 0];
        b0.y = acc[i][1] + bias[colBase + tx * 8 + 1];
        b0.z = acc[i][2] + bias[colBase + tx * 8 + 2];
        b0.w = acc[i][3] + bias[colBase + tx * 8 + 3];
        b1.x = acc[i][4] + bias[colBase + tx * 8 + 4];
        b1.y = acc[i][5] + bias[colBase + tx * 8 + 5];
        b1.z = acc[i][6] + bias[colBase + tx * 8 + 6];
        b1.w = acc[i][7] + bias[colBase + tx * 8 + 7];
        *(float4*)(orow)     = b0;
        *(float4*)(orow + 4) = b1;
    }
}

// ---------------------------------------------------------------------------
// Kernel 4: hd = Y @ hd_w + hd_b   (N=12). One warp per row.
// hd_w staged transposed [12][256] in SMEM -> conflict-free strided reads.
// ---------------------------------------------------------------------------
__global__ void __launch_bounds__(256) hd_kernel(const float* __restrict__ Y,
                                                 const float* __restrict__ W,
                                                 const float* __restrict__ bias,
                                                 float* __restrict__ out) {
    __shared__ float ws[N_HD * N_H];  // ws[j*256 + h]
    __shared__ float bs[N_HD];
    const int tid = threadIdx.x;
    for (int i = tid; i < N_HD * N_H; i += 256) {
        int h = i / N_HD, j = i - h * N_HD;
        ws[j * N_H + h] = W[i];
    }
    if (tid < N_HD) bs[tid] = bias[tid];
    __syncthreads();

    const int warp = tid >> 5, lane = tid & 31;
    const long row = (long)blockIdx.x * 8 + warp;

    float acc[N_HD];
    #pragma unroll
    for (int j = 0; j < N_HD; j++) acc[j] = 0.0f;

    const float* yr = Y + row * N_H;
    #pragma unroll
    for (int i = 0; i < 8; i++) {
        int h = i * 32 + lane;           // coalesced LDG, conflict-free LDS
        float yv = yr[h];
        #pragma unroll
        for (int j = 0; j < N_HD; j++)
            acc[j] = fmaf(yv, ws[j * N_H + h], acc[j]);
    }
    #pragma unroll
    for (int j = 0; j < N_HD; j++) {
        #pragma unroll
        for (int o = 16; o > 0; o >>= 1)
            acc[j] += __shfl_xor_sync(0xFFFFFFFFu, acc[j], o);
    }
    if (lane == 0) {
        float* o = out + row * N_HD;
        #pragma unroll
        for (int j = 0; j < N_HD; j++) o[j] = acc[j] + bs[j];
    }
}

// ---------------------------------------------------------------------------
extern "C" void kernel_launch(void* const* d_in, const int* in_sizes, int n_in,
                              void* d_out, int out_size) {
    const float* x    = (const float*)d_in[0];   // [T,B,3]
    const float* ic   = (const float*)d_in[1];   // [B,268]
    const float* iw   = (const float*)d_in[2];   // [3,256]
    const float* l    = (const float*)d_in[3];   // [256]
    const float* b    = (const float*)d_in[4];   // [256]
    const float* sew  = (const float*)d_in[5];   // [268,256]
    const float* seb  = (const float*)d_in[6];   // [256]
    const float* cew  = (const float*)d_in[7];   // [268,256]
    const float* ceb  = (const float*)d_in[8];   // [256]
    const float* pcw  = (const float*)d_in[9];   // [256,256]
    const float* pcb  = (const float*)d_in[10];  // [256]
    const float* hdw  = (const float*)d_in[11];  // [256,12]
    const float* hdb  = (const float*)d_in[12];  // [12]
    float* out = (float*)d_out;

    // 1) initial carry
    init_kernel<<<BATCH, N_H>>>(ic, sew, seb, cew, ceb);

    // 2) recurrence: fills BOT (y), RNN (y), CELL (s)
    rec_kernel<<<BATCH, 64>>>(x, iw, l, b, out);

    // 3) hd logits from y (RNN region)
    hd_kernel<<<M_ROWS / 8, 256>>>(out + OFF_RNN, hdw, hdb, out + OFF_HD);

    // 4) pc logits from y
    dim3 pcGrid(M_ROWS / BM, N_PC / BN);
    pc_gemm<<<pcGrid, 256>>>(out + OFF_RNN, pcw, pcb, out + OFF_PC);
}

// round 3
// speedup vs baseline: 1.6311x; 1.6311x over previous
#include <cuda_runtime.h>
#include <cuda_bf16.h>
#include <math.h>
#include <stdint.h>

// Problem constants
#define T_STEPS 1000
#define BATCH   128
#define N_IN    3
#define N_H     256
#define N_PC    256
#define N_HD    12
#define N_IC    268
#define M_ROWS  (T_STEPS * BATCH)   // 128000

// Output layout (float32, concatenated in reference tuple order)
#define OFF_HD   0L
#define OFF_PC   (OFF_HD  + (long)T_STEPS * BATCH * N_HD)
#define OFF_BOT  (OFF_PC  + (long)T_STEPS * BATCH * N_PC)
#define OFF_RNN  (OFF_BOT + (long)T_STEPS * BATCH * N_H)
#define OFF_CELL (OFF_RNN + (long)T_STEPS * BATCH * N_H)

// Tile swizzle: rows of 512B; XOR 16B-unit index bits with (row&7).
// phys_byte(r, kb) = r*512 + (kb ^ ((r&7)<<4)); conflict-free for ldmatrix.
#define TSWZ(kb, r) ((kb) ^ (((r) & 7) << 4))

// ---------------------------------------------------------------------------
// Device-global scratch (allocation-free)
// ---------------------------------------------------------------------------
__device__ float g_h0[BATCH * N_H];
__device__ float g_c0[BATCH * N_H];
// Y bf16, pre-swizzled tile images: tile t = [128 batch rows][256 h], 64KB each.
__device__ __nv_bfloat16 g_yimg[(long)T_STEPS * 128 * 256];
// W hi/lo bf16 images per N-half: [hi 64KB | lo 64KB] contiguous (128KB per half).
__device__ __nv_bfloat16 g_wimg[2][65536];

// ---------------------------------------------------------------------------
// PTX helpers (all base-arch: sm_80/75 features only)
// ---------------------------------------------------------------------------
__device__ __forceinline__ uint32_t smem_u32(const void* p) {
    uint32_t a;
    asm("{ .reg .u64 t; cvta.to.shared.u64 t, %1; cvt.u32.u64 %0, t; }" : "=r"(a) : "l"(p));
    return a;
}
__device__ __forceinline__ void cp_async16(uint32_t dst, const void* src) {
    asm volatile("cp.async.cg.shared.global [%0], [%1], 16;" :: "r"(dst), "l"(src) : "memory");
}
__device__ __forceinline__ void cp_async_wait_all() {
    asm volatile("cp.async.commit_group;\ncp.async.wait_group 0;" ::: "memory");
}
__device__ __forceinline__ void ldsm4(uint32_t& r0, uint32_t& r1, uint32_t& r2, uint32_t& r3,
                                      uint32_t addr) {
    asm volatile("ldmatrix.sync.aligned.m8n8.x4.shared.b16 {%0,%1,%2,%3}, [%4];"
                 : "=r"(r0), "=r"(r1), "=r"(r2), "=r"(r3) : "r"(addr));
}
__device__ __forceinline__ void mma16816(float* c, const uint32_t* a, uint32_t b0, uint32_t b1) {
    asm volatile("mma.sync.aligned.m16n8k16.row.col.f32.bf16.bf16.f32 "
                 "{%0,%1,%2,%3}, {%4,%5,%6,%7}, {%8,%9}, {%0,%1,%2,%3};"
                 : "+f"(c[0]), "+f"(c[1]), "+f"(c[2]), "+f"(c[3])
                 : "r"(a[0]), "r"(a[1]), "r"(a[2]), "r"(a[3]), "r"(b0), "r"(b1));
}

// ---------------------------------------------------------------------------
// Kernel 1: initial conditions
// ---------------------------------------------------------------------------
__global__ void init_kernel(const float* __restrict__ ic,
                            const float* __restrict__ sew, const float* __restrict__ seb,
                            const float* __restrict__ cew, const float* __restrict__ ceb) {
    __shared__ float icr[N_IC];
    int b = blockIdx.x;
    int h = threadIdx.x;
    for (int i = h; i < N_IC; i += N_H) icr[i] = ic[b * N_IC + i];
    __syncthreads();

    float accS = seb[h];
    float accC = ceb[h];
    #pragma unroll 4
    for (int k = 0; k < N_IC; k++) {
        float v = icr[k];
        accS = fmaf(v, sew[k * N_H + h], accS);
        accC = fmaf(v, cew[k * N_H + h], accC);
    }
    g_h0[b * N_H + h] = 1.0f / (1.0f + expf(-accS));
    g_c0[b * N_H + h] = 1.0f / (1.0f + expf(-accC));
}

// ---------------------------------------------------------------------------
// Kernel 2: W -> (hi, lo) bf16, pre-swizzled images per N-half.
// W stored [k=256][n=256] row-major; image row = n (within half), cols = k.
// ---------------------------------------------------------------------------
__global__ void wconv_kernel(const float* __restrict__ W) {
    int k = blockIdx.x;    // 0..255
    int n = threadIdx.x;   // 0..255
    float w = W[k * 256 + n];
    __nv_bfloat16 hi = __float2bfloat16(w);
    __nv_bfloat16 lo = __float2bfloat16(w - __bfloat162float(hi));
    int nh = n >> 7, nl = n & 127;
    int byteoff = nl * 512 + TSWZ(k * 2, nl);
    g_wimg[nh][byteoff >> 1]           = hi;
    g_wimg[nh][32768 + (byteoff >> 1)] = lo;
}

// ---------------------------------------------------------------------------
// Kernel 3: recurrence. grid=(128,2), 32 threads, 4 h per thread.
// Writes fp32 y -> BOT,RNN; s -> CELL; bf16 y -> g_yimg (pre-swizzled tiles).
// ---------------------------------------------------------------------------
__global__ void __launch_bounds__(32, 16) rec_kernel(const float* __restrict__ x,
                                                     const float* __restrict__ iw,
                                                     const float* __restrict__ lvec,
                                                     const float* __restrict__ bvec,
                                                     float* __restrict__ out) {
    __shared__ float xs[T_STEPS * N_IN];  // 12 KB
    const int b    = blockIdx.x;
    const int half = blockIdx.y;
    const int tid  = threadIdx.x;
    const int hbase = half * 128 + tid * 4;

    for (int i = tid; i < T_STEPS * N_IN; i += 32) {
        int t = i / N_IN, c = i - t * N_IN;
        xs[i] = x[((long)t * BATCH + b) * N_IN + c];
    }

    float w0[4], w1[4], w2[4], lv[4], bv[4], y[4], s[4];
    #pragma unroll
    for (int i = 0; i < 4; i++) {
        int h = hbase + i;
        w0[i] = iw[0 * N_H + h];
        w1[i] = iw[1 * N_H + h];
        w2[i] = iw[2 * N_H + h];
        lv[i] = lvec[h];
        bv[i] = bvec[h];
        y[i]  = g_h0[b * N_H + h];
        s[i]  = g_c0[b * N_H + h];
    }
    __syncthreads();

    float4* yout1 = (float4*)(out + OFF_BOT);
    float4* yout2 = (float4*)(out + OFF_RNN);
    float4* sout  = (float4*)(out + OFF_CELL);

    // pre-swizzled element offset (bf16 units) within a Y tile for (row=b, col=hbase)
    const int inoff = (b * 512 + TSWZ(hbase * 2, b)) >> 1;

    for (int t = 0; t < T_STEPS; t++) {
        const float x0 = xs[t * 3 + 0];
        const float x1 = xs[t * 3 + 1];
        const float x2 = xs[t * 3 + 2];
        #pragma unroll
        for (int i = 0; i < 4; i++) {
            float xw  = fmaf(x2, w2[i], fmaf(x1, w1[i], x0 * w0[i]));
            float pre = xw + y[i] + lv[i] * s[i] * (1.0f - y[i]);
            s[i] = fmaxf(pre, 0.0f);
            y[i] = (s[i] + bv[i] > 0.0f) ? 1.0f : 0.0f;
        }
        long idx4 = (((long)t * BATCH + b) * N_H + hbase) >> 2;
        float4 yv = make_float4(y[0], y[1], y[2], y[3]);
        float4 sv = make_float4(s[0], s[1], s[2], s[3]);
        yout1[idx4] = yv;
        yout2[idx4] = yv;
        sout[idx4]  = sv;

        __nv_bfloat162 p0 = __floats2bfloat162_rn(y[0], y[1]);
        __nv_bfloat162 p1 = __floats2bfloat162_rn(y[2], y[3]);
        uint2 pk;
        pk.x = *(uint32_t*)&p0;
        pk.y = *(uint32_t*)&p1;
        *(uint2*)(g_yimg + (long)t * 32768 + inoff) = pk;
    }
}

// ---------------------------------------------------------------------------
// Kernel 4: pc GEMM via HMMA (mma.sync bf16). grid=(1000,2), 256 thr, 192KB SMEM.
// D[128,128] = Y_tile @ (W_hi + W_lo)^T-half, fp32 accum, + bias.
// ---------------------------------------------------------------------------
#define SM_A  0
#define SM_BH 65536
#define SM_TOT 196608

__global__ void __launch_bounds__(256) pc_gemm(const float* __restrict__ pcb,
                                               float* __restrict__ out) {
    extern __shared__ char smem[];
    uint32_t sb = smem_u32(smem);
    const int tid = threadIdx.x, wid = tid >> 5, lane = tid & 31;
    const int m = blockIdx.x, nh = blockIdx.y;
    const int warp_m = wid & 3, warp_n = wid >> 2;

    // Linear bulk copy of pre-swizzled images: A tile 64KB, W half (hi|lo) 128KB
    {
        const char* gA = (const char*)(g_yimg + (long)m * 32768);
        const char* gW = (const char*)(g_wimg[nh]);
        #pragma unroll
        for (int i = 0; i < 16; i++)
            cp_async16(sb + SM_A + (tid + i * 256) * 16, gA + (tid + i * 256) * 16);
        #pragma unroll
        for (int i = 0; i < 32; i++)
            cp_async16(sb + SM_BH + (tid + i * 256) * 16, gW + (tid + i * 256) * 16);
        cp_async_wait_all();
    }
    __syncthreads();

    float acc[2][8][4];
    #pragma unroll
    for (int i = 0; i < 2; i++)
        #pragma unroll
        for (int j = 0; j < 8; j++)
            #pragma unroll
            for (int q = 0; q < 4; q++) acc[i][j][q] = 0.0f;

    const int arow0 = warp_m * 32 + (lane & 15);
    const int brow0 = warp_n * 64 + (lane & 15);
    const int ksub  = (lane >> 4) * 16;

    #pragma unroll
    for (int pass = 0; pass < 2; pass++) {
        const uint32_t bbase = sb + SM_BH + pass * 65536;
        #pragma unroll
        for (int k16 = 0; k16 < 16; k16++) {
            const int kb = k16 * 32 + ksub;
            uint32_t a[2][4], bfr[4][4];
            #pragma unroll
            for (int mi = 0; mi < 2; mi++) {
                int r = arow0 + mi * 16;
                ldsm4(a[mi][0], a[mi][1], a[mi][2], a[mi][3],
                      sb + SM_A + r * 512 + TSWZ(kb, r));
            }
            #pragma unroll
            for (int ni = 0; ni < 4; ni++) {
                int r = brow0 + ni * 16;
                ldsm4(bfr[ni][0], bfr[ni][1], bfr[ni][2], bfr[ni][3],
                      bbase + r * 512 + TSWZ(kb, r));
            }
            #pragma unroll
            for (int mi = 0; mi < 2; mi++)
                #pragma unroll
                for (int ni = 0; ni < 4; ni++) {
                    mma16816(acc[mi][ni * 2],     a[mi], bfr[ni][0], bfr[ni][2]);
                    mma16816(acc[mi][ni * 2 + 1], a[mi], bfr[ni][1], bfr[ni][3]);
                }
        }
    }

    // Epilogue: direct float2 stores (+bias). c0,c1: row g; c2,c3: row g+8.
    const int g   = lane >> 2;
    const int c2  = (lane & 3) * 2;
    const long rowBase = (long)m * 128 + warp_m * 32;
    const int  colBase = nh * 128 + warp_n * 64;

    float2 bias2[8];
    #pragma unroll
    for (int ni = 0; ni < 8; ni++) {
        bias2[ni].x = __ldg(pcb + colBase + ni * 8 + c2);
        bias2[ni].y = __ldg(pcb + colBase + ni * 8 + c2 + 1);
    }

    #pragma unroll
    for (int mi = 0; mi < 2; mi++) {
        float* r0 = out + (rowBase + mi * 16 + g) * N_PC + colBase + c2;
        float* r1 = r0 + 8 * N_PC;
        #pragma unroll
        for (int ni = 0; ni < 8; ni++) {
            *(float2*)(r0 + ni * 8) = make_float2(acc[mi][ni][0] + bias2[ni].x,
                                                  acc[mi][ni][1] + bias2[ni].y);
            *(float2*)(r1 + ni * 8) = make_float2(acc[mi][ni][2] + bias2[ni].x,
                                                  acc[mi][ni][3] + bias2[ni].y);
        }
    }
}

// ---------------------------------------------------------------------------
// Kernel 5: hd = Y @ hd_w + hd_b (N=12). One warp per row.
// ---------------------------------------------------------------------------
__global__ void __launch_bounds__(256) hd_kernel(const float* __restrict__ Y,
                                                 const float* __restrict__ W,
                                                 const float* __restrict__ bias,
                                                 float* __restrict__ out) {
    __shared__ float ws[N_HD * N_H];
    __shared__ float bs[N_HD];
    const int tid = threadIdx.x;
    for (int i = tid; i < N_HD * N_H; i += 256) {
        int h = i / N_HD, j = i - h * N_HD;
        ws[j * N_H + h] = W[i];
    }
    if (tid < N_HD) bs[tid] = bias[tid];
    __syncthreads();

    const int warp = tid >> 5, lane = tid & 31;
    const long row = (long)blockIdx.x * 8 + warp;

    float acc[N_HD];
    #pragma unroll
    for (int j = 0; j < N_HD; j++) acc[j] = 0.0f;

    const float* yr = Y + row * N_H;
    #pragma unroll
    for (int i = 0; i < 8; i++) {
        int h = i * 32 + lane;
        float yv = yr[h];
        #pragma unroll
        for (int j = 0; j < N_HD; j++)
            acc[j] = fmaf(yv, ws[j * N_H + h], acc[j]);
    }
    #pragma unroll
    for (int j = 0; j < N_HD; j++) {
        #pragma unroll
        for (int o = 16; o > 0; o >>= 1)
            acc[j] += __shfl_xor_sync(0xFFFFFFFFu, acc[j], o);
    }
    if (lane == 0) {
        float* o = out + row * N_HD;
        #pragma unroll
        for (int j = 0; j < N_HD; j++) o[j] = acc[j] + bs[j];
    }
}

// ---------------------------------------------------------------------------
extern "C" void kernel_launch(void* const* d_in, const int* in_sizes, int n_in,
                              void* d_out, int out_size) {
    const float* x    = (const float*)d_in[0];
    const float* ic   = (const float*)d_in[1];
    const float* iw   = (const float*)d_in[2];
    const float* l    = (const float*)d_in[3];
    const float* b    = (const float*)d_in[4];
    const float* sew  = (const float*)d_in[5];
    const float* seb  = (const float*)d_in[6];
    const float* cew  = (const float*)d_in[7];
    const float* ceb  = (const float*)d_in[8];
    const float* pcw  = (const float*)d_in[9];
    const float* pcb  = (const float*)d_in[10];
    const float* hdw  = (const float*)d_in[11];
    const float* hdb  = (const float*)d_in[12];
    float* out = (float*)d_out;

    cudaFuncSetAttribute(pc_gemm, cudaFuncAttributeMaxDynamicSharedMemorySize, SM_TOT);

    init_kernel<<<BATCH, N_H>>>(ic, sew, seb, cew, ceb);
    wconv_kernel<<<256, 256>>>(pcw);
    rec_kernel<<<dim3(BATCH, 2), 32>>>(x, iw, l, b, out);
    hd_kernel<<<M_ROWS / 8, 256>>>(out + OFF_RNN, hdw, hdb, out + OFF_HD);
    pc_gemm<<<dim3(T_STEPS, 2), 256, SM_TOT>>>(pcb, out + OFF_PC);
}

// round 4
// speedup vs baseline: 2.4711x; 1.5149x over previous
#include <cuda_runtime.h>
#include <cuda_bf16.h>
#include <math.h>
#include <stdint.h>

// Problem constants
#define T_STEPS 1000
#define BATCH   128
#define N_IN    3
#define N_H     256
#define N_PC    256
#define N_HD    12
#define N_IC    268
#define M_ROWS  (T_STEPS * BATCH)   // 128000

// Output layout (float32, concatenated in reference tuple order)
#define OFF_HD   0L
#define OFF_PC   (OFF_HD  + (long)T_STEPS * BATCH * N_HD)
#define OFF_BOT  (OFF_PC  + (long)T_STEPS * BATCH * N_PC)
#define OFF_RNN  (OFF_BOT + (long)T_STEPS * BATCH * N_H)
#define OFF_CELL (OFF_RNN + (long)T_STEPS * BATCH * N_H)

// Tile swizzle: rows of 512B; XOR byte-offset bits[4:6] with (row&7).
#define TSWZ(kb, r) ((kb) ^ (((r) & 7) << 4))

// ---------------------------------------------------------------------------
// Device-global scratch (allocation-free)
// ---------------------------------------------------------------------------
__device__ float g_h0[BATCH * N_H];
__device__ float g_c0[BATCH * N_H];
// Y bf16, pre-swizzled tile images: tile t = [128 batch rows][256 h], 64KB each.
__device__ __nv_bfloat16 g_yimg[(long)T_STEPS * 128 * 256];
// pc W hi/lo bf16 images per N-half: [hi 64KB | lo 64KB] contiguous.
__device__ __nv_bfloat16 g_wimg[2][65536];
// hd W hi/lo bf16 image: 16 rows (12 used) x 256 k: [hi 8KB | lo 8KB].
__device__ __nv_bfloat16 g_hdimg[8192];

// ---------------------------------------------------------------------------
// PTX helpers (base-arch only)
// ---------------------------------------------------------------------------
__device__ __forceinline__ uint32_t smem_u32(const void* p) {
    uint32_t a;
    asm("{ .reg .u64 t; cvta.to.shared.u64 t, %1; cvt.u32.u64 %0, t; }" : "=r"(a) : "l"(p));
    return a;
}
__device__ __forceinline__ void cp_async16(uint32_t dst, const void* src) {
    asm volatile("cp.async.cg.shared.global [%0], [%1], 16;" :: "r"(dst), "l"(src) : "memory");
}
__device__ __forceinline__ void cp_async_wait_all() {
    asm volatile("cp.async.commit_group;\ncp.async.wait_group 0;" ::: "memory");
}
__device__ __forceinline__ void ldsm4(uint32_t& r0, uint32_t& r1, uint32_t& r2, uint32_t& r3,
                                      uint32_t addr) {
    asm volatile("ldmatrix.sync.aligned.m8n8.x4.shared.b16 {%0,%1,%2,%3}, [%4];"
                 : "=r"(r0), "=r"(r1), "=r"(r2), "=r"(r3) : "r"(addr));
}
__device__ __forceinline__ void mma16816(float* c, const uint32_t* a, uint32_t b0, uint32_t b1) {
    asm volatile("mma.sync.aligned.m16n8k16.row.col.f32.bf16.bf16.f32 "
                 "{%0,%1,%2,%3}, {%4,%5,%6,%7}, {%8,%9}, {%0,%1,%2,%3};"
                 : "+f"(c[0]), "+f"(c[1]), "+f"(c[2]), "+f"(c[3])
                 : "r"(a[0]), "r"(a[1]), "r"(a[2]), "r"(a[3]), "r"(b0), "r"(b1));
}

// ---------------------------------------------------------------------------
// Kernel 1: initial conditions
// ---------------------------------------------------------------------------
__global__ void init_kernel(const float* __restrict__ ic,
                            const float* __restrict__ sew, const float* __restrict__ seb,
                            const float* __restrict__ cew, const float* __restrict__ ceb) {
    __shared__ float icr[N_IC];
    int b = blockIdx.x;
    int h = threadIdx.x;
    for (int i = h; i < N_IC; i += N_H) icr[i] = ic[b * N_IC + i];
    __syncthreads();

    float accS = seb[h];
    float accC = ceb[h];
    #pragma unroll 4
    for (int k = 0; k < N_IC; k++) {
        float v = icr[k];
        accS = fmaf(v, sew[k * N_H + h], accS);
        accC = fmaf(v, cew[k * N_H + h], accC);
    }
    g_h0[b * N_H + h] = 1.0f / (1.0f + expf(-accS));
    g_c0[b * N_H + h] = 1.0f / (1.0f + expf(-accC));
}

// ---------------------------------------------------------------------------
// Kernel 2a: pc W -> (hi, lo) bf16, pre-swizzled images per N-half.
// ---------------------------------------------------------------------------
__global__ void wconv_kernel(const float* __restrict__ W) {
    int k = blockIdx.x;    // 0..255
    int n = threadIdx.x;   // 0..255
    float w = W[k * 256 + n];
    __nv_bfloat16 hi = __float2bfloat16(w);
    __nv_bfloat16 lo = __float2bfloat16(w - __bfloat162float(hi));
    int nh = n >> 7, nl = n & 127;
    int byteoff = nl * 512 + TSWZ(k * 2, nl);
    g_wimg[nh][byteoff >> 1]           = hi;
    g_wimg[nh][32768 + (byteoff >> 1)] = lo;
}

// Kernel 2b: hd W [256,12] -> padded 16-row hi/lo image.
__global__ void wconv_hd_kernel(const float* __restrict__ W) {
    int n = blockIdx.x;    // 0..15
    int k = threadIdx.x;   // 0..255
    float w = (n < N_HD) ? W[k * N_HD + n] : 0.0f;
    __nv_bfloat16 hi = __float2bfloat16(w);
    __nv_bfloat16 lo = __float2bfloat16(w - __bfloat162float(hi));
    int byteoff = n * 512 + TSWZ(k * 2, n);
    g_hdimg[byteoff >> 1]          = hi;
    g_hdimg[4096 + (byteoff >> 1)] = lo;
}

// ---------------------------------------------------------------------------
// Kernel 3: recurrence. grid=128 (one per batch), 256 threads (one per h).
// ---------------------------------------------------------------------------
__global__ void __launch_bounds__(256) rec_kernel(const float* __restrict__ x,
                                                  const float* __restrict__ iw,
                                                  const float* __restrict__ lvec,
                                                  const float* __restrict__ bvec,
                                                  float* __restrict__ out) {
    __shared__ float xs[T_STEPS * N_IN];  // 12 KB
    const int b = blockIdx.x;
    const int h = threadIdx.x;

    for (int i = h; i < T_STEPS * N_IN; i += 256) {
        int t = i / N_IN, c = i - t * N_IN;
        xs[i] = x[((long)t * BATCH + b) * N_IN + c];
    }

    const float w0 = iw[0 * N_H + h];
    const float w1 = iw[1 * N_H + h];
    const float w2 = iw[2 * N_H + h];
    const float lv = lvec[h];
    const float bv = bvec[h];
    float y = g_h0[b * N_H + h];
    float s = g_c0[b * N_H + h];
    __syncthreads();

    float* yp1 = out + OFF_BOT + (long)b * N_H + h;
    float* yp2 = out + OFF_RNN + (long)b * N_H + h;
    float* sp  = out + OFF_CELL + (long)b * N_H + h;
    __nv_bfloat16* yi = g_yimg + ((b * 512 + TSWZ(h * 2, b)) >> 1);

    const long strideT = (long)BATCH * N_H;  // 32768

    for (int t = 0; t < T_STEPS; t++) {
        const float x0 = xs[t * 3 + 0];
        const float x1 = xs[t * 3 + 1];
        const float x2 = xs[t * 3 + 2];
        float xw  = fmaf(x2, w2, fmaf(x1, w1, x0 * w0));
        float pre = xw + y + lv * s * (1.0f - y);
        s = fmaxf(pre, 0.0f);
        y = (s + bv > 0.0f) ? 1.0f : 0.0f;

        long o = (long)t * strideT;
        yp1[o] = y;
        yp2[o] = y;
        sp[o]  = s;
        yi[(long)t * 32768] = __float2bfloat16(y);
    }
}

// ---------------------------------------------------------------------------
// Kernel 4: pc GEMM via HMMA + fused hd. grid=(1000,2), 256 thr, 208KB SMEM.
// nh==0 blocks also compute hd[128,12] using warp_n==0 warps.
// ---------------------------------------------------------------------------
#define SM_A   0
#define SM_BH  65536
#define SM_HD  196608
#define SM_TOT 212992

__global__ void __launch_bounds__(256) pc_gemm(const float* __restrict__ pcb,
                                               const float* __restrict__ hdb,
                                               float* __restrict__ out) {
    extern __shared__ char smem[];
    uint32_t sb = smem_u32(smem);
    const int tid = threadIdx.x, wid = tid >> 5, lane = tid & 31;
    const int m = blockIdx.x, nh = blockIdx.y;
    const int warp_m = wid & 3, warp_n = wid >> 2;
    const bool do_hd = (nh == 0) && (warp_n == 0);

    // Linear bulk copies of pre-swizzled images
    {
        const char* gA = (const char*)(g_yimg + (long)m * 32768);
        const char* gW = (const char*)(g_wimg[nh]);
        #pragma unroll
        for (int i = 0; i < 16; i++)
            cp_async16(sb + SM_A + (tid + i * 256) * 16, gA + (tid + i * 256) * 16);
        #pragma unroll
        for (int i = 0; i < 32; i++)
            cp_async16(sb + SM_BH + (tid + i * 256) * 16, gW + (tid + i * 256) * 16);
        if (nh == 0) {
            const char* gH = (const char*)g_hdimg;
            #pragma unroll
            for (int i = 0; i < 4; i++)
                cp_async16(sb + SM_HD + (tid + i * 256) * 16, gH + (tid + i * 256) * 16);
        }
        cp_async_wait_all();
    }
    __syncthreads();

    float acc[2][8][4];
    #pragma unroll
    for (int i = 0; i < 2; i++)
        #pragma unroll
        for (int j = 0; j < 8; j++)
            #pragma unroll
            for (int q = 0; q < 4; q++) acc[i][j][q] = 0.0f;
    float acch[2][2][4];
    #pragma unroll
    for (int i = 0; i < 2; i++)
        #pragma unroll
        for (int j = 0; j < 2; j++)
            #pragma unroll
            for (int q = 0; q < 4; q++) acch[i][j][q] = 0.0f;

    const int arow0 = warp_m * 32 + (lane & 15);
    const int brow0 = warp_n * 64 + (lane & 15);
    const int hrow0 = (lane & 15);
    const int ksub  = (lane >> 4) * 16;

    #pragma unroll
    for (int pass = 0; pass < 2; pass++) {
        const uint32_t bbase = sb + SM_BH + pass * 65536;
        const uint32_t hbase = sb + SM_HD + pass * 8192;
        #pragma unroll
        for (int k16 = 0; k16 < 16; k16++) {
            const int kb = k16 * 32 + ksub;
            uint32_t a[2][4], bfr[4][4];
            #pragma unroll
            for (int mi = 0; mi < 2; mi++) {
                int r = arow0 + mi * 16;
                ldsm4(a[mi][0], a[mi][1], a[mi][2], a[mi][3],
                      sb + SM_A + r * 512 + TSWZ(kb, r));
            }
            #pragma unroll
            for (int ni = 0; ni < 4; ni++) {
                int r = brow0 + ni * 16;
                ldsm4(bfr[ni][0], bfr[ni][1], bfr[ni][2], bfr[ni][3],
                      bbase + r * 512 + TSWZ(kb, r));
            }
            #pragma unroll
            for (int mi = 0; mi < 2; mi++)
                #pragma unroll
                for (int ni = 0; ni < 4; ni++) {
                    mma16816(acc[mi][ni * 2],     a[mi], bfr[ni][0], bfr[ni][2]);
                    mma16816(acc[mi][ni * 2 + 1], a[mi], bfr[ni][1], bfr[ni][3]);
                }
            if (do_hd) {
                uint32_t hb[4];
                ldsm4(hb[0], hb[1], hb[2], hb[3],
                      hbase + hrow0 * 512 + TSWZ(kb, hrow0));
                #pragma unroll
                for (int mi = 0; mi < 2; mi++) {
                    mma16816(acch[mi][0], a[mi], hb[0], hb[2]);
                    mma16816(acch[mi][1], a[mi], hb[1], hb[3]);
                }
            }
        }
    }

    // Epilogue: pc. c0,c1: row g; c2,c3: row g+8.
    const int g  = lane >> 2;
    const int c2 = (lane & 3) * 2;
    const long rowBase = (long)m * 128 + warp_m * 32;
    const int  colBase = nh * 128 + warp_n * 64;

    float2 bias2[8];
    #pragma unroll
    for (int ni = 0; ni < 8; ni++) {
        bias2[ni].x = __ldg(pcb + colBase + ni * 8 + c2);
        bias2[ni].y = __ldg(pcb + colBase + ni * 8 + c2 + 1);
    }

    float* outpc = out + OFF_PC;
    #pragma unroll
    for (int mi = 0; mi < 2; mi++) {
        float* r0 = outpc + (rowBase + mi * 16 + g) * N_PC + colBase + c2;
        float* r1 = r0 + 8 * N_PC;
        #pragma unroll
        for (int ni = 0; ni < 8; ni++) {
            *(float2*)(r0 + ni * 8) = make_float2(acc[mi][ni][0] + bias2[ni].x,
                                                  acc[mi][ni][1] + bias2[ni].y);
            *(float2*)(r1 + ni * 8) = make_float2(acc[mi][ni][2] + bias2[ni].x,
                                                  acc[mi][ni][3] + bias2[ni].y);
        }
    }

    // Epilogue: hd (cols 0..11 of the padded 16)
    if (do_hd) {
        float* outhd = out + OFF_HD;
        float hb0x = __ldg(hdb + c2);
        float hb0y = __ldg(hdb + c2 + 1);
        float hb1x = 0.0f, hb1y = 0.0f;
        if (c2 < 4) {
            hb1x = __ldg(hdb + 8 + c2);
            hb1y = __ldg(hdb + 8 + c2 + 1);
        }
        #pragma unroll
        for (int mi = 0; mi < 2; mi++) {
            long r = rowBase + mi * 16 + g;
            float* o0 = outhd + r * N_HD;
            float* o1 = o0 + 8L * N_HD;
            *(float2*)(o0 + c2) = make_float2(acch[mi][0][0] + hb0x, acch[mi][0][1] + hb0y);
            *(float2*)(o1 + c2) = make_float2(acch[mi][0][2] + hb0x, acch[mi][0][3] + hb0y);
            if (c2 < 4) {
                *(float2*)(o0 + 8 + c2) = make_float2(acch[mi][1][0] + hb1x, acch[mi][1][1] + hb1y);
                *(float2*)(o1 + 8 + c2) = make_float2(acch[mi][1][2] + hb1x, acch[mi][1][3] + hb1y);
            }
        }
    }
}

// ---------------------------------------------------------------------------
extern "C" void kernel_launch(void* const* d_in, const int* in_sizes, int n_in,
                              void* d_out, int out_size) {
    const float* x    = (const float*)d_in[0];
    const float* ic   = (const float*)d_in[1];
    const float* iw   = (const float*)d_in[2];
    const float* l    = (const float*)d_in[3];
    const float* b    = (const float*)d_in[4];
    const float* sew  = (const float*)d_in[5];
    const float* seb  = (const float*)d_in[6];
    const float* cew  = (const float*)d_in[7];
    const float* ceb  = (const float*)d_in[8];
    const float* pcw  = (const float*)d_in[9];
    const float* pcb  = (const float*)d_in[10];
    const float* hdw  = (const float*)d_in[11];
    const float* hdb  = (const float*)d_in[12];
    float* out = (float*)d_out;

    cudaFuncSetAttribute(pc_gemm, cudaFuncAttributeMaxDynamicSharedMemorySize, SM_TOT);

    init_kernel<<<BATCH, N_H>>>(ic, sew, seb, cew, ceb);
    wconv_kernel<<<256, 256>>>(pcw);
    wconv_hd_kernel<<<16, 256>>>(hdw);
    rec_kernel<<<BATCH, 256>>>(x, iw, l, b, out);
    pc_gemm<<<dim3(T_STEPS, 2), 256, SM_TOT>>>(pcb, hdb, out);
}